// round 6
// baseline (speedup 1.0000x reference)
#include <cuda_runtime.h>
#include <cuda_bf16.h>
#include <math_constants.h>

#define KNN 32
#define NPB 128            // atoms per molecule (contiguous, 128-aligned)
#define NPW 2              // nodes per warp: node0 -> ALU flavor, node1 -> FP flavor
#define WARPS_PER_CTA 4
#define NODES_PER_CTA (NPW * WARPS_PER_CTA)  // 8
typedef unsigned long long u64;
#define SENT 0xFFFFFFFFFFFFFFFFULL

__device__ __forceinline__ u64 shflx64(u64 v, int m) {
  return __shfl_xor_sync(0xFFFFFFFFu, v, m);
}

// ---------------- Key flavors ----------------
// Both implement the same total order as jax.lax.top_k(-masked):
// (d2 ascending, index ascending), padding == +inf sorts last with stable idx.

// ALU-pipe flavor: packed u64 (d2_bits << 32) | idx. Compare = ISETP.X chain.
struct KeyU64 {
  u64 v;
  __device__ __forceinline__ static KeyU64 make(bool ok, float d2, int j) {
    KeyU64 k;
    k.v = ok ? (((u64)__float_as_uint(d2) << 32) | (unsigned)j) : SENT;
    return k;
  }
  __device__ __forceinline__ bool less(const KeyU64& o) const { return v < o.v; }
  __device__ __forceinline__ KeyU64 shfl(int m) const {
    KeyU64 k; k.v = shflx64(v, m); return k;
  }
  __device__ __forceinline__ bool is_pad() const { return v == SENT; }
  __device__ __forceinline__ int idx() const { return (int)(unsigned)v; }
};

// FP-pipe flavor: (float d2, float idx) with lexicographic FSETP/FSEL compare.
// d2 >= 0 so float order == bit order used by the reference's top_k.
struct KeyFP {
  float f, i;
  __device__ __forceinline__ static KeyFP make(bool ok, float d2, int j) {
    KeyFP k;
    k.f = ok ? d2 : CUDART_INF_F;
    k.i = (float)j;
    return k;
  }
  __device__ __forceinline__ bool less(const KeyFP& o) const {
    return (f < o.f) || ((f == o.f) && (i < o.i));
  }
  __device__ __forceinline__ KeyFP shfl(int m) const {
    KeyFP k;
    k.f = __shfl_xor_sync(0xFFFFFFFFu, f, m);
    k.i = __shfl_xor_sync(0xFFFFFFFFu, i, m);
    return k;
  }
  __device__ __forceinline__ bool is_pad() const { return isinf(f); }
  __device__ __forceinline__ int idx() const { return (int)i; }
};

// ---------------- Network primitives ----------------
template <class K>
__device__ __forceinline__ void cas(K& a, int m, bool keepMin) {
  K o = a.shfl(m);
  const bool lt = a.less(o);
  a = (lt == keepMin) ? a : o;
}

template <bool ASC, class K>
__device__ __forceinline__ void sort32(K& a, int lane) {
#pragma unroll
  for (int k = 2; k <= 32; k <<= 1) {
#pragma unroll
    for (int j = k >> 1; j > 0; j >>= 1) {
      const bool base = (((lane & j) == 0) == ((lane & k) == 0));
      cas(a, j, base == ASC);
    }
  }
}

// a ascending, b descending -> 32 smallest of the 64, sorted (ASC or DESC).
// concat(asc, desc) is bitonic; elementwise min is its half-cleaner low half.
template <bool ASC, class K>
__device__ __forceinline__ K keep_low(K a_asc, K b_desc, int lane) {
  K t = a_asc.less(b_desc) ? a_asc : b_desc;
#pragma unroll
  for (int j = 16; j > 0; j >>= 1) {
    cas(t, j, ((lane & j) == 0) == ASC);
  }
  return t;
}

// Full top-32-sorted selection from 4 key columns.
template <class K>
__device__ __forceinline__ K select_top32(K r0, K r1, K r2, K r3, int lane) {
  sort32<true>(r0, lane);
  sort32<false>(r1, lane);
  sort32<true>(r2, lane);
  sort32<false>(r3, lane);
  K t01 = keep_low<true>(r0, r1, lane);   // ascending
  K t23 = keep_low<false>(r2, r3, lane);  // descending
  return keep_low<true>(t01, t23, lane);  // ascending final
}

// d2 arithmetic replicates the reference's (XLA, contraction-on) rounding:
//   sq  = fma(z,z, fma(y,y, x*x))
//   dot = fma(z,z', fma(y,y', x*x'))
//   d2  = max((sq_i + sq_j) - 2*dot, 0)
template <class K>
__device__ __forceinline__ void process_node(
    int n, int molbase, int lane, const float* sx, const float* sy,
    const float* sz, const float* ssq, const int* sb, float* out,
    long long NK) {
  const int self = n & (NPB - 1);
  const float x = sx[self], y = sy[self], z = sz[self];
  const float sq = ssq[self];
  const int bme = sb[self];

  K r[4];
#pragma unroll
  for (int m = 0; m < 4; m++) {
    const int j = m * 32 + lane;
    const float dot =
        __fmaf_rn(z, sz[j], __fmaf_rn(y, sy[j], __fmul_rn(x, sx[j])));
    float d2 = __fsub_rn(__fadd_rn(sq, ssq[j]), __fmul_rn(2.0f, dot));
    d2 = fmaxf(d2, 0.0f);
    r[m] = K::make((sb[j] == bme) && (d2 <= 25.0f), d2, j);
  }

  const K key = select_top32(r[0], r[1], r[2], r[3], lane);

  const int j = key.is_pad() ? self : key.idx();
  const float vx = x - sx[j];
  const float vy = y - sy[j];
  const float vz = z - sz[j];
  const float ssv = __fmaf_rn(vz, vz, __fmaf_rn(vy, vy, __fmul_rn(vx, vx)));
  const float w = (j == self) ? 0.0f : __fsqrt_rn(ssv);

  const int e = n * KNN + lane;
  out[e]          = (float)n;
  out[NK + e]     = (float)(molbase + j);
  out[2 * NK + e] = w;
  float* __restrict__ ov = out + 3 * NK + 3LL * e;
  ov[0] = vx; ov[1] = vy; ov[2] = vz;
}

__global__ __launch_bounds__(NPB) void radius_graph_kernel(
    const float* __restrict__ pos, const int* __restrict__ batch,
    float* __restrict__ out, int N) {
  __shared__ float sx[NPB], sy[NPB], sz[NPB], ssq[NPB];
  __shared__ int sb[NPB];

  const int tid  = threadIdx.x;
  const int lane = tid & 31;
  const int wid  = tid >> 5;
  const int nbase = blockIdx.x * NODES_PER_CTA;
  const int molbase = nbase & ~(NPB - 1);

  {
    const float ax = pos[3 * (molbase + tid) + 0];
    const float ay = pos[3 * (molbase + tid) + 1];
    const float az = pos[3 * (molbase + tid) + 2];
    sx[tid] = ax; sy[tid] = ay; sz[tid] = az;
    ssq[tid] = __fmaf_rn(az, az, __fmaf_rn(ay, ay, __fmul_rn(ax, ax)));
    sb[tid]  = batch[molbase + tid];
  }
  __syncthreads();

  const long long NK = (long long)N * KNN;
  const int n0 = nbase + wid * NPW;

  // Node 0 on the ALU pipe (u64 keys), node 1 on the FP pipe (float keys):
  // the two independent comparator networks interleave across both pipes.
  process_node<KeyU64>(n0 + 0, molbase, lane, sx, sy, sz, ssq, sb, out, NK);
  process_node<KeyFP >(n0 + 1, molbase, lane, sx, sy, sz, ssq, sb, out, NK);
}

extern "C" void kernel_launch(void* const* d_in, const int* in_sizes, int n_in,
                              void* d_out, int out_size) {
  const float* pos  = (const float*)d_in[0];
  const int* batch  = (const int*)d_in[1];
  const int N = in_sizes[0] / 3;            // pos is [N,3]
  const int nblocks = N / NODES_PER_CTA;    // 8 nodes per CTA, 2 per warp
  radius_graph_kernel<<<nblocks, NPB>>>(pos, batch, (float*)d_out, N);
}